// round 10
// baseline (speedup 1.0000x reference)
#include <cuda_runtime.h>
#include <cuda_bf16.h>

typedef unsigned long long u64;
typedef unsigned int u32;

#define NH    8
#define DK    32
#define HH    56
#define WWID  56
#define HW    3136
#define HW2   1568      // HW/2
#define BB    2
#define CC    256
#define NTILES 49       // 3136 / 64 exactly
#define PADB  80        // smem row stride in BYTES (40 bf16)
#define BUFB  (64*PADB) // one tile buffer bytes
#define LOG2E 1.4426950408889634f
#define ONESB 0x3f803f80u
#define XROWB 544       // proj smem x-row stride in bytes (512 data + 32 pad)
#define MROWS 64        // proj m-tile rows per CTA

// ---------------- scratch (__device__ globals; no allocs allowed) ----------------
__device__ __align__(16) __nv_bfloat16 g_xh[(size_t)BB*HW*CC];   // permuted frag layout
__device__ __align__(16) __nv_bfloat16 g_Wc[3*CC*512];           // [z][n][kc][t4] -> {h0,h1,l0,l1} u32s
__device__ __align__(16) __nv_bfloat16 g_Qh[(size_t)BB*NH*HW*DK];   // pre-scaled by log2e
__device__ __align__(16) __nv_bfloat16 g_Kb[(size_t)BB*NH*HW*DK];
__device__ __align__(16) __nv_bfloat16 g_Vb[(size_t)BB*NH*HW*DK];
__device__ u32 g_wadd[HW2];   // packed bf16x2 exponent addends for key multiplicity

// ---------------- helpers ----------------
__device__ __forceinline__ u32 pkbf(float hi, float lo) {
    u32 r; asm("cvt.rn.bf16x2.f32 %0, %1, %2;" : "=r"(r) : "f"(hi), "f"(lo)); return r;
}
__device__ __forceinline__ float ex2f(float x) {
    float r; asm("ex2.approx.f32 %0, %1;" : "=f"(r) : "f"(x)); return r;
}
__device__ __forceinline__ void ldsm4(u32* r, u32 addr) {
    asm volatile("ldmatrix.sync.aligned.m8n8.x4.shared.b16 {%0,%1,%2,%3}, [%4];"
        : "=r"(r[0]),"=r"(r[1]),"=r"(r[2]),"=r"(r[3]) : "r"(addr));
}
__device__ __forceinline__ void ldsm4t(u32* r, u32 addr) {
    asm volatile("ldmatrix.sync.aligned.m8n8.x4.trans.shared.b16 {%0,%1,%2,%3}, [%4];"
        : "=r"(r[0]),"=r"(r[1]),"=r"(r[2]),"=r"(r[3]) : "r"(addr));
}
__device__ __forceinline__ void mmabf(float* d, const u32* a, u32 b0, u32 b1) {
    asm volatile("mma.sync.aligned.m16n8k16.row.col.f32.bf16.bf16.f32 "
        "{%0,%1,%2,%3}, {%4,%5,%6,%7}, {%8,%9}, {%0,%1,%2,%3};"
        : "+f"(d[0]),"+f"(d[1]),"+f"(d[2]),"+f"(d[3])
        : "r"(a[0]),"r"(a[1]),"r"(a[2]),"r"(a[3]), "r"(b0),"r"(b1));
}
__device__ __forceinline__ void cpa16(u32 dst, const void* src) {
    asm volatile("cp.async.cg.shared.global [%0], [%1], 16;" :: "r"(dst), "l"(src));
}
// permuted u32-index within a 128-u32 row: frag order so (t4, t4+4) are adjacent
__device__ __forceinline__ int permj(int j) {
    int t = j & 7, kc = j >> 3;
    return kc*8 + ((t < 4) ? 2*t : 2*(t-4) + 1);
}
__device__ __forceinline__ int lww(int v) {
    return ((v >= 1 && v <= 3) || (v >= 52 && v <= 54)) ? 1 : 0;
}

// ---------------- prep: multiplicity addend table ----------------
__global__ __launch_bounds__(256) void prep_wadd() {
    int i = blockIdx.x*256 + threadIdx.x;
    if (i >= HW2) return;
    int k0 = 2*i, k1 = k0 + 1;
    int y0 = k0 / WWID, x0 = k0 - y0*WWID;
    int y1 = k1 / WWID, x1 = k1 - y1*WWID;
    u32 w0 = (u32)(lww(y0) + lww(x0));
    u32 w1 = (u32)(lww(y1) + lww(x1));
    g_wadd[i] = (w0 << 7) | (w1 << 23);
}

// ---------------- prep: x -> bf16 hi (permuted) ----------------
__global__ __launch_bounds__(256) void prep_x(const float* __restrict__ x) {
    int idx = blockIdx.x*256 + threadIdx.x;       // over BB*HW*64 float4s
    if (idx >= BB*HW*64) return;
    int row = idx >> 6, i = idx & 63;
    float4 v = reinterpret_cast<const float4*>(x)[idx];
    u32 H0 = pkbf(v.y, v.x);
    u32 H1 = pkbf(v.w, v.z);
    u32* xh = reinterpret_cast<u32*>(g_xh) + (size_t)row*128;
    xh[permj(2*i)]     = H0;
    xh[permj(2*i + 1)] = H1;
}

// ---------------- prep: W -> transposed/permuted, interleaved hi|lo u128 entries ----------------
__global__ __launch_bounds__(256) void prep_w(const float* __restrict__ Wq,
                                              const float* __restrict__ Wk,
                                              const float* __restrict__ Wv) {
    __shared__ float T[32][33];
    int z = blockIdx.z;
    const float* W = (z == 0) ? Wq : (z == 1) ? Wk : Wv;
    float sc = (z == 0) ? LOG2E : 1.0f;
    int k0 = blockIdx.y*32, n0 = blockIdx.x*32;
    int tx = threadIdx.x & 31, ty = threadIdx.x >> 5;   // 32x8
    #pragma unroll
    for (int i = 0; i < 4; ++i)
        T[ty + 8*i][tx] = W[(size_t)(k0 + ty + 8*i)*CC + n0 + tx];
    __syncthreads();
    #pragma unroll
    for (int i = 0; i < 4; ++i) {
        int n = n0 + ty + 8*i, k = k0 + tx;
        float v = T[tx][ty + 8*i] * sc;
        __nv_bfloat16 h = __float2bfloat16(v);
        __nv_bfloat16 l = __float2bfloat16(v - __bfloat162float(h));
        int j = k >> 1;
        int kc = j >> 3, t = j & 7;
        int pj = (t < 4) ? 2*t : 2*(t - 4) + 1;
        int t4 = pj >> 1, sub = pj & 1;
        size_t e = (((size_t)z*CC + n)*16 + kc)*4 + t4;   // u128 entry
        size_t slot = e*8 + sub*2 + (k & 1);              // h at bytes 0-7
        g_Wc[slot]     = h;
        g_Wc[slot + 4] = l;                                // l at bytes 8-15
    }
}

// ---------------- tensor-core projections: 64-row m-tile, smem-staged x ----------------
// z=0: Q -> g_Qh (log2e-scaled) ; z=1: K -> g_Kb ; z=2: V -> g_Vb
__global__ __launch_bounds__(256) void proj_mma(const float* __restrict__ bq,
                                                const float* __restrict__ bk,
                                                const float* __restrict__ bv) {
    __shared__ __align__(16) char sX[MROWS*XROWB];        // 34.8 KB x tile
    int z = blockIdx.y;
    int m0 = blockIdx.x * MROWS;
    int tid = threadIdx.x, wid = tid >> 5, lane = tid & 31;
    int g = lane >> 2, t4 = lane & 3;
    int n0 = wid * 32;
    const float* bias = (z == 0) ? bq : (z == 1) ? bk : bv;
    float bscale = (z == 0) ? LOG2E : 1.0f;
    __nv_bfloat16* dst = (z == 0) ? g_Qh : (z == 1) ? g_Kb : g_Vb;

    // stage x tile: MROWS rows x 512B, 16B chunks
    u32 sxb = (u32)__cvta_generic_to_shared(sX);
    const char* xsrc = (const char*)g_xh + (size_t)m0*512;
    #pragma unroll
    for (int rep = 0; rep < MROWS*32/256; ++rep) {
        int i = tid + rep*256;
        int row = i >> 5, c = i & 31;
        cpa16(sxb + row*XROWB + c*16, xsrc + (size_t)row*512 + c*16);
    }
    asm volatile("cp.async.commit_group;");

    const uint4* wc = reinterpret_cast<const uint4*>(g_Wc) + (size_t)z*CC*64;

    float acc[4][4][4];
    #pragma unroll
    for (int mf = 0; mf < 4; ++mf)
        #pragma unroll
        for (int nf = 0; nf < 4; ++nf)
            #pragma unroll
            for (int c = 0; c < 4; ++c) acc[mf][nf][c] = 0.f;

    asm volatile("cp.async.wait_group 0;");
    __syncthreads();

    const char* sxp = sX;
    #pragma unroll 2
    for (int kc = 0; kc < 16; ++kc) {
        u32 ah[4][4];
        #pragma unroll
        for (int mf = 0; mf < 4; ++mf) {
            u64 va0 = *(const u64*)(sxp + (mf*16 + g)    *XROWB + kc*32 + t4*8);
            u64 va1 = *(const u64*)(sxp + (mf*16 + g + 8)*XROWB + kc*32 + t4*8);
            ah[mf][0] = (u32)va0; ah[mf][2] = (u32)(va0 >> 32);
            ah[mf][1] = (u32)va1; ah[mf][3] = (u32)(va1 >> 32);
        }
        #pragma unroll
        for (int nf = 0; nf < 4; ++nf) {
            int nrow = n0 + nf*8 + g;
            uint4 w = wc[(size_t)nrow*64 + kc*4 + t4];
            #pragma unroll
            for (int mf = 0; mf < 4; ++mf) {
                mmabf(acc[mf][nf], ah[mf], w.x, w.y);
                mmabf(acc[mf][nf], ah[mf], w.z, w.w);
            }
        }
    }

    #pragma unroll
    for (int nf = 0; nf < 4; ++nf) {
        int n = n0 + nf*8 + 2*t4;
        float bi0 = bias[n]*bscale, bi1 = bias[n + 1]*bscale;
        int hh = n >> 5, dd = n & 31;
        #pragma unroll
        for (int mf = 0; mf < 4; ++mf) {
            #pragma unroll
            for (int half = 0; half < 2; ++half) {
                int r = m0 + mf*16 + half*8 + g;
                int b = r / HW, q = r - b*HW;
                float v0 = acc[mf][nf][half*2]     + bi0;
                float v1 = acc[mf][nf][half*2 + 1] + bi1;
                u32 Hp = pkbf(v1, v0);
                size_t o = ((size_t)(b*NH + hh)*HW + q)*16 + (dd >> 1);
                reinterpret_cast<u32*>(dst)[o] = Hp;
            }
        }
    }
}

// ---------------- tensor-core flash attention: 8 warps, 16 q/warp, unique keys ----------------
__global__ __launch_bounds__(256, 3) void flash_kernel(const float* __restrict__ x,
                                                       const float* __restrict__ gamma,
                                                       float* __restrict__ out) {
    __shared__ __align__(16) __nv_bfloat16 sK[2*BUFB/2];
    __shared__ __align__(16) __nv_bfloat16 sV[2*BUFB/2];
    __shared__ u32 sWadd[HW2];
    int bh = blockIdx.y;
    int b = bh >> 3, h = bh & 7;
    int tid = threadIdx.x, wid = tid >> 5, lane = tid & 31;
    int g = lane >> 2, t4 = lane & 3;
    int qbase = blockIdx.x*128 + wid*16;

    for (int i = tid; i < HW2; i += 256) sWadd[i] = g_wadd[i];

    u32 qh[2][4];
    {
        int r0 = qbase + g;     if (r0 >= HW) r0 = 0;
        int r1 = qbase + g + 8; if (r1 >= HW) r1 = 0;
        const u32* h0 = (const u32*)(g_Qh + (((size_t)bh)*HW + r0)*DK);
        const u32* h1 = (const u32*)(g_Qh + (((size_t)bh)*HW + r1)*DK);
        #pragma unroll
        for (int kf = 0; kf < 2; ++kf) {
            qh[kf][0] = h0[kf*8 + t4];
            qh[kf][1] = h1[kf*8 + t4];
            qh[kf][2] = h0[kf*8 + 4 + t4];
            qh[kf][3] = h1[kf*8 + 4 + t4];
        }
    }

    float O[4][4];
    float Dl[4] = {0.f, 0.f, 0.f, 0.f};   // lsum accumulator via ones-MMA
    #pragma unroll
    for (int nf = 0; nf < 4; ++nf)
        #pragma unroll
        for (int c = 0; c < 4; ++c) O[nf][c] = 0.f;

    const float4* Kg = (const float4*)(g_Kb + ((size_t)bh)*HW*DK);
    const float4* Vg = (const float4*)(g_Vb + ((size_t)bh)*HW*DK);
    u32 skb = (u32)__cvta_generic_to_shared(sK);
    u32 svb = (u32)__cvta_generic_to_shared(sV);

    u32 koff[4], voff[4];
    #pragma unroll
    for (int nf = 0; nf < 4; ++nf) {
        koff[nf] = skb + (nf*8 + (lane & 7))*PADB + (lane >> 3)*16;
        voff[nf] = svb + lane*PADB + nf*16;
    }
    u32 wk = skb + (tid >> 2)*PADB + (tid & 3)*16;
    u32 wv = svb + (tid >> 2)*PADB + (tid & 3)*16;

    // prologue: tile 0 -> buf 0
    cpa16(wk, Kg + tid);
    cpa16(wv, Vg + tid);
    asm volatile("cp.async.commit_group;");

    for (int tile = 0; tile < NTILES; ++tile) {
        u32 bofs = (tile & 1)*BUFB;
        asm volatile("cp.async.wait_group 0;");
        __syncthreads();
        if (tile + 1 < NTILES) {
            u32 nofs = ((tile + 1) & 1)*BUFB;
            cpa16(wk + nofs, Kg + (size_t)(tile + 1)*256 + tid);
            cpa16(wv + nofs, Vg + (size_t)(tile + 1)*256 + tid);
            asm volatile("cp.async.commit_group;");
        }
        const u32* wrow = sWadd + tile*32 + t4;

        #pragma unroll
        for (int half = 0; half < 2; ++half) {
            u32 hofs = bofs + half*(32*PADB);
            float S[4][4];
            #pragma unroll
            for (int nf = 0; nf < 4; ++nf)
                #pragma unroll
                for (int c = 0; c < 4; ++c) S[nf][c] = 0.f;

            #pragma unroll
            for (int nf = 0; nf < 4; ++nf) {
                u32 bhr[4];
                ldsm4(bhr, koff[nf] + hofs);
                mmabf(S[nf], qh[0], bhr[0], bhr[1]);
                mmabf(S[nf], qh[1], bhr[2], bhr[3]);
            }

            u32 wa[4];
            #pragma unroll
            for (int jj = 0; jj < 4; ++jj) wa[jj] = wrow[half*16 + jj*4];

            u32 Pa[2][4];
            #pragma unroll
            for (int jj = 0; jj < 4; ++jj) {
                float p0 = ex2f(S[jj][0]);
                float p1 = ex2f(S[jj][1]);
                float p2 = ex2f(S[jj][2]);
                float p3 = ex2f(S[jj][3]);
                // exact multiplicity weighting: +w in the bf16 exponent field
                Pa[jj>>1][(jj&1)*2 + 0] = pkbf(p1, p0) + wa[jj];
                Pa[jj>>1][(jj&1)*2 + 1] = pkbf(p3, p2) + wa[jj];
            }

            #pragma unroll
            for (int nfd = 0; nfd < 4; ++nfd) {
                u32 vb[4];
                ldsm4t(vb, voff[nfd] + hofs);
                mmabf(O[nfd], Pa[0], vb[0], vb[1]);
                mmabf(O[nfd], Pa[1], vb[2], vb[3]);
            }
            // weighted row-sum (softmax denominator) on the tensor pipe
            mmabf(Dl, Pa[0], ONESB, ONESB);
            mmabf(Dl, Pa[1], ONESB, ONESB);
        }
    }

    float gam = gamma[0];
    {
        float inv0 = 1.f / Dl[0];
        float inv1 = 1.f / Dl[2];
        int r0 = qbase + g;
        int r1 = r0 + 8;
        #pragma unroll
        for (int nfd = 0; nfd < 4; ++nfd) {
            int col = h*DK + nfd*8 + 2*t4;
            if (r0 < HW) {
                size_t base = ((size_t)(b*HW + r0))*CC + col;
                out[base]     = fmaf(gam, O[nfd][0]*inv0, x[base]);
                out[base + 1] = fmaf(gam, O[nfd][1]*inv0, x[base + 1]);
            }
            if (r1 < HW) {
                size_t base = ((size_t)(b*HW + r1))*CC + col;
                out[base]     = fmaf(gam, O[nfd][2]*inv1, x[base]);
                out[base + 1] = fmaf(gam, O[nfd][3]*inv1, x[base + 1]);
            }
        }
    }
}

extern "C" void kernel_launch(void* const* d_in, const int* in_sizes, int n_in,
                              void* d_out, int out_size) {
    const float* x     = (const float*)d_in[0];
    const float* Wq    = (const float*)d_in[1];
    const float* bq    = (const float*)d_in[2];
    const float* Wk    = (const float*)d_in[3];
    const float* bk    = (const float*)d_in[4];
    const float* Wv    = (const float*)d_in[5];
    const float* bv    = (const float*)d_in[6];
    const float* gamma = (const float*)d_in[7];
    float* out = (float*)d_out;

    prep_wadd<<<(HW2 + 255)/256, 256>>>();
    prep_x<<<(BB*HW*64 + 255)/256, 256>>>(x);
    prep_w<<<dim3(8, 8, 3), 256>>>(Wq, Wk, Wv);
    proj_mma<<<dim3(BB*HW/MROWS, 3), 256>>>(bq, bk, bv);
    flash_kernel<<<dim3((HW + 127)/128, BB*NH), 256>>>(x, gamma, out);
}

// round 11
// speedup vs baseline: 1.0273x; 1.0273x over previous
#include <cuda_runtime.h>
#include <cuda_bf16.h>

typedef unsigned long long u64;
typedef unsigned int u32;

#define NH    8
#define DK    32
#define HH    56
#define WWID  56
#define HW    3136
#define HW2   1568      // HW/2
#define BB    2
#define CC    256
#define NTILES 49       // 3136 / 64 exactly
#define PADB  80        // smem row stride in BYTES (40 bf16)
#define BUFB  (64*PADB) // one tile buffer bytes
#define LOG2E 1.4426950408889634f
#define ONESB 0x3f803f80u
#define XROWB 544       // proj smem x-row stride in bytes (512 data + 32 pad)

// ---------------- scratch (__device__ globals; no allocs allowed) ----------------
__device__ __align__(16) __nv_bfloat16 g_xh[(size_t)BB*HW*CC];   // permuted frag layout
__device__ __align__(16) __nv_bfloat16 g_Wc[3*CC*512];           // [z][n][kc][t4] -> {h0,h1,l0,l1} u32s
__device__ __align__(16) __nv_bfloat16 g_Qh[(size_t)BB*NH*HW*DK];   // pre-scaled by log2e
__device__ __align__(16) __nv_bfloat16 g_Kb[(size_t)BB*NH*HW*DK];
__device__ __align__(16) __nv_bfloat16 g_Vb[(size_t)BB*NH*HW*DK];
__device__ __align__(16) u32 g_wadd[HW2];   // [tile][half][t4][jj] packed bf16x2 exponent addends

// ---------------- helpers ----------------
__device__ __forceinline__ u32 pkbf(float hi, float lo) {
    u32 r; asm("cvt.rn.bf16x2.f32 %0, %1, %2;" : "=r"(r) : "f"(hi), "f"(lo)); return r;
}
__device__ __forceinline__ float ex2f(float x) {
    float r; asm("ex2.approx.f32 %0, %1;" : "=f"(r) : "f"(x)); return r;
}
__device__ __forceinline__ void ldsm4(u32* r, u32 addr) {
    asm volatile("ldmatrix.sync.aligned.m8n8.x4.shared.b16 {%0,%1,%2,%3}, [%4];"
        : "=r"(r[0]),"=r"(r[1]),"=r"(r[2]),"=r"(r[3]) : "r"(addr));
}
__device__ __forceinline__ void ldsm4t(u32* r, u32 addr) {
    asm volatile("ldmatrix.sync.aligned.m8n8.x4.trans.shared.b16 {%0,%1,%2,%3}, [%4];"
        : "=r"(r[0]),"=r"(r[1]),"=r"(r[2]),"=r"(r[3]) : "r"(addr));
}
__device__ __forceinline__ void mmabf(float* d, const u32* a, u32 b0, u32 b1) {
    asm volatile("mma.sync.aligned.m16n8k16.row.col.f32.bf16.bf16.f32 "
        "{%0,%1,%2,%3}, {%4,%5,%6,%7}, {%8,%9}, {%0,%1,%2,%3};"
        : "+f"(d[0]),"+f"(d[1]),"+f"(d[2]),"+f"(d[3])
        : "r"(a[0]),"r"(a[1]),"r"(a[2]),"r"(a[3]), "r"(b0),"r"(b1));
}
// D = A*B + Z (separate C operand; Z holds a persistent zero quad -> no per-use MOVs)
__device__ __forceinline__ void mmabf_z(float* d, const u32* a, u32 b0, u32 b1, const float* z) {
    asm volatile("mma.sync.aligned.m16n8k16.row.col.f32.bf16.bf16.f32 "
        "{%0,%1,%2,%3}, {%4,%5,%6,%7}, {%8,%9}, {%10,%11,%12,%13};"
        : "=f"(d[0]),"=f"(d[1]),"=f"(d[2]),"=f"(d[3])
        : "r"(a[0]),"r"(a[1]),"r"(a[2]),"r"(a[3]), "r"(b0),"r"(b1),
          "f"(z[0]),"f"(z[1]),"f"(z[2]),"f"(z[3]));
}
__device__ __forceinline__ void cpa16(u32 dst, const void* src) {
    asm volatile("cp.async.cg.shared.global [%0], [%1], 16;" :: "r"(dst), "l"(src));
}
// permuted u32-index within a 128-u32 row: frag order so (t4, t4+4) are adjacent
__device__ __forceinline__ int permj(int j) {
    int t = j & 7, kc = j >> 3;
    return kc*8 + ((t < 4) ? 2*t : 2*(t-4) + 1);
}
__device__ __forceinline__ int lww(int v) {
    return ((v >= 1 && v <= 3) || (v >= 52 && v <= 54)) ? 1 : 0;
}

// ---------------- prep: x -> bf16 hi (permuted) + multiplicity table (fused) ----------------
__global__ __launch_bounds__(256) void prep_x(const float* __restrict__ x) {
    int idx = blockIdx.x*256 + threadIdx.x;       // over BB*HW*64 float4s
    if (idx < HW2) {
        // element e=idx of [tile][half][t4][jj] layout holds pair p = tile*32+half*16+jj*4+t4
        int jj = idx & 3, t4i = (idx >> 2) & 3, half = (idx >> 4) & 1, tile = idx >> 5;
        int p = tile*32 + half*16 + jj*4 + t4i;
        int k0 = 2*p, k1 = k0 + 1;
        int y0 = k0 / WWID, x0 = k0 - y0*WWID;
        int y1 = k1 / WWID, x1 = k1 - y1*WWID;
        u32 w0 = (u32)(lww(y0) + lww(x0));
        u32 w1 = (u32)(lww(y1) + lww(x1));
        g_wadd[idx] = (w0 << 7) | (w1 << 23);
    }
    if (idx >= BB*HW*64) return;
    int row = idx >> 6, i = idx & 63;
    float4 v = reinterpret_cast<const float4*>(x)[idx];
    u32 H0 = pkbf(v.y, v.x);
    u32 H1 = pkbf(v.w, v.z);
    u32* xh = reinterpret_cast<u32*>(g_xh) + (size_t)row*128;
    xh[permj(2*i)]     = H0;
    xh[permj(2*i + 1)] = H1;
}

// ---------------- prep: W -> transposed/permuted, interleaved hi|lo u128 entries ----------------
__global__ __launch_bounds__(256) void prep_w(const float* __restrict__ Wq,
                                              const float* __restrict__ Wk,
                                              const float* __restrict__ Wv) {
    __shared__ float T[32][33];
    int z = blockIdx.z;
    const float* W = (z == 0) ? Wq : (z == 1) ? Wk : Wv;
    float sc = (z == 0) ? LOG2E : 1.0f;
    int k0 = blockIdx.y*32, n0 = blockIdx.x*32;
    int tx = threadIdx.x & 31, ty = threadIdx.x >> 5;   // 32x8
    #pragma unroll
    for (int i = 0; i < 4; ++i)
        T[ty + 8*i][tx] = W[(size_t)(k0 + ty + 8*i)*CC + n0 + tx];
    __syncthreads();
    #pragma unroll
    for (int i = 0; i < 4; ++i) {
        int n = n0 + ty + 8*i, k = k0 + tx;
        float v = T[tx][ty + 8*i] * sc;
        __nv_bfloat16 h = __float2bfloat16(v);
        __nv_bfloat16 l = __float2bfloat16(v - __bfloat162float(h));
        int j = k >> 1;
        int kc = j >> 3, t = j & 7;
        int pj = (t < 4) ? 2*t : 2*(t - 4) + 1;
        int t4 = pj >> 1, sub = pj & 1;
        size_t e = (((size_t)z*CC + n)*16 + kc)*4 + t4;   // u128 entry
        size_t slot = e*8 + sub*2 + (k & 1);              // h at bytes 0-7
        g_Wc[slot]     = h;
        g_Wc[slot + 4] = l;                                // l at bytes 8-15
    }
}

// ---------------- tensor-core projections: smem-staged x, u128 W loads (round-9 proven) ----------------
// z=0: Q -> g_Qh (log2e-scaled) ; z=1: K -> g_Kb ; z=2: V -> g_Vb
__global__ __launch_bounds__(256) void proj_mma(const float* __restrict__ bq,
                                                const float* __restrict__ bk,
                                                const float* __restrict__ bv) {
    __shared__ __align__(16) char sX[32*XROWB];           // 17.4 KB x tile
    int z = blockIdx.y;
    int m0 = blockIdx.x * 32;
    int tid = threadIdx.x, wid = tid >> 5, lane = tid & 31;
    int g = lane >> 2, t4 = lane & 3;
    int n0 = wid * 32;
    const float* bias = (z == 0) ? bq : (z == 1) ? bk : bv;
    float bscale = (z == 0) ? LOG2E : 1.0f;
    __nv_bfloat16* dst = (z == 0) ? g_Qh : (z == 1) ? g_Kb : g_Vb;

    // stage x tile: 32 rows x 512B, 16B chunks
    u32 sxb = (u32)__cvta_generic_to_shared(sX);
    const char* xsrc = (const char*)g_xh + (size_t)m0*512;
    #pragma unroll
    for (int rep = 0; rep < 4; ++rep) {
        int i = tid + rep*256;                  // 0..1023
        int row = i >> 5, c = i & 31;
        cpa16(sxb + row*XROWB + c*16, xsrc + (size_t)row*512 + c*16);
    }
    asm volatile("cp.async.commit_group;");

    int rl[4];
    #pragma unroll
    for (int t = 0; t < 4; ++t)
        rl[t] = (t >> 1)*16 + (t & 1)*8 + g;    // local rows

    const uint4* wc = reinterpret_cast<const uint4*>(g_Wc) + (size_t)z*CC*64;

    float acc[2][4][4];
    #pragma unroll
    for (int mf = 0; mf < 2; ++mf)
        #pragma unroll
        for (int nf = 0; nf < 4; ++nf)
            #pragma unroll
            for (int c = 0; c < 4; ++c) acc[mf][nf][c] = 0.f;

    asm volatile("cp.async.wait_group 0;");
    __syncthreads();

    const char* sxp = sX;
    #pragma unroll 4
    for (int kc = 0; kc < 16; ++kc) {
        u32 ah[2][4];
        #pragma unroll
        for (int mf = 0; mf < 2; ++mf) {
            u64 va0 = *(const u64*)(sxp + rl[mf*2]    *XROWB + kc*32 + t4*8);
            u64 va1 = *(const u64*)(sxp + rl[mf*2 + 1]*XROWB + kc*32 + t4*8);
            ah[mf][0] = (u32)va0; ah[mf][2] = (u32)(va0 >> 32);
            ah[mf][1] = (u32)va1; ah[mf][3] = (u32)(va1 >> 32);
        }
        #pragma unroll
        for (int nf = 0; nf < 4; ++nf) {
            int nrow = n0 + nf*8 + g;
            uint4 w = wc[(size_t)nrow*64 + kc*4 + t4];
            #pragma unroll
            for (int mf = 0; mf < 2; ++mf) {
                mmabf(acc[mf][nf], ah[mf], w.x, w.y);
                mmabf(acc[mf][nf], ah[mf], w.z, w.w);
            }
        }
    }

    #pragma unroll
    for (int nf = 0; nf < 4; ++nf) {
        int n = n0 + nf*8 + 2*t4;
        float bi0 = bias[n]*bscale, bi1 = bias[n + 1]*bscale;
        int hh = n >> 5, dd = n & 31;
        #pragma unroll
        for (int mf = 0; mf < 2; ++mf) {
            #pragma unroll
            for (int half = 0; half < 2; ++half) {
                int t = mf*2 + half;
                int r = m0 + rl[t];
                int b = r / HW, q = r - b*HW;
                float v0 = acc[mf][nf][half*2]     + bi0;
                float v1 = acc[mf][nf][half*2 + 1] + bi1;
                u32 Hp = pkbf(v1, v0);
                size_t o = ((size_t)(b*NH + hh)*HW + q)*16 + (dd >> 1);
                reinterpret_cast<u32*>(dst)[o] = Hp;
            }
        }
    }
}

// ---------------- tensor-core flash attention: 8 warps, 16 q/warp, unique keys ----------------
__global__ __launch_bounds__(256, 3) void flash_kernel(const float* __restrict__ x,
                                                       const float* __restrict__ gamma,
                                                       float* __restrict__ out) {
    __shared__ __align__(16) __nv_bfloat16 sK[2*BUFB/2];
    __shared__ __align__(16) __nv_bfloat16 sV[2*BUFB/2];
    __shared__ __align__(16) u32 sWadd[HW2];
    int bh = blockIdx.y;
    int b = bh >> 3, h = bh & 7;
    int tid = threadIdx.x, wid = tid >> 5, lane = tid & 31;
    int g = lane >> 2, t4 = lane & 3;
    int qbase = blockIdx.x*128 + wid*16;

    for (int i = tid; i < HW2; i += 256) sWadd[i] = g_wadd[i];

    u32 qh[2][4];
    {
        int r0 = qbase + g;     if (r0 >= HW) r0 = 0;
        int r1 = qbase + g + 8; if (r1 >= HW) r1 = 0;
        const u32* h0 = (const u32*)(g_Qh + (((size_t)bh)*HW + r0)*DK);
        const u32* h1 = (const u32*)(g_Qh + (((size_t)bh)*HW + r1)*DK);
        #pragma unroll
        for (int kf = 0; kf < 2; ++kf) {
            qh[kf][0] = h0[kf*8 + t4];
            qh[kf][1] = h1[kf*8 + t4];
            qh[kf][2] = h0[kf*8 + 4 + t4];
            qh[kf][3] = h1[kf*8 + 4 + t4];
        }
    }

    float O[4][4];
    float Dl[4] = {0.f, 0.f, 0.f, 0.f};   // lsum accumulator via ones-MMA
    float zq[4] = {0.f, 0.f, 0.f, 0.f};   // persistent zero quad for mmabf_z
    #pragma unroll
    for (int nf = 0; nf < 4; ++nf)
        #pragma unroll
        for (int c = 0; c < 4; ++c) O[nf][c] = 0.f;

    const float4* Kg = (const float4*)(g_Kb + ((size_t)bh)*HW*DK);
    const float4* Vg = (const float4*)(g_Vb + ((size_t)bh)*HW*DK);
    u32 skb = (u32)__cvta_generic_to_shared(sK);
    u32 svb = (u32)__cvta_generic_to_shared(sV);
    const uint4* sW4 = reinterpret_cast<const uint4*>(sWadd);

    u32 koff[4], voff[4];
    #pragma unroll
    for (int nf = 0; nf < 4; ++nf) {
        koff[nf] = skb + (nf*8 + (lane & 7))*PADB + (lane >> 3)*16;
        voff[nf] = svb + lane*PADB + nf*16;
    }
    u32 wk = skb + (tid >> 2)*PADB + (tid & 3)*16;
    u32 wv = svb + (tid >> 2)*PADB + (tid & 3)*16;

    // prologue: tile 0 -> buf 0
    cpa16(wk, Kg + tid);
    cpa16(wv, Vg + tid);
    asm volatile("cp.async.commit_group;");

    for (int tile = 0; tile < NTILES; ++tile) {
        u32 bofs = (tile & 1)*BUFB;
        asm volatile("cp.async.wait_group 0;");
        __syncthreads();
        if (tile + 1 < NTILES) {
            u32 nofs = ((tile + 1) & 1)*BUFB;
            cpa16(wk + nofs, Kg + (size_t)(tile + 1)*256 + tid);
            cpa16(wv + nofs, Vg + (size_t)(tile + 1)*256 + tid);
            asm volatile("cp.async.commit_group;");
        }

        #pragma unroll
        for (int half = 0; half < 2; ++half) {
            u32 hofs = bofs + half*(32*PADB);
            float S[4][4];

            #pragma unroll
            for (int nf = 0; nf < 4; ++nf) {
                u32 bhr[4];
                ldsm4(bhr, koff[nf] + hofs);
                mmabf_z(S[nf], qh[0], bhr[0], bhr[1], zq);
                mmabf(S[nf], qh[1], bhr[2], bhr[3]);
            }

            uint4 wv4 = sW4[(tile*2 + half)*4 + t4];
            u32 wa[4] = {wv4.x, wv4.y, wv4.z, wv4.w};

            u32 Pa[2][4];
            #pragma unroll
            for (int jj = 0; jj < 4; ++jj) {
                float p0 = ex2f(S[jj][0]);
                float p1 = ex2f(S[jj][1]);
                float p2 = ex2f(S[jj][2]);
                float p3 = ex2f(S[jj][3]);
                // exact multiplicity weighting: +w in the bf16 exponent field
                Pa[jj>>1][(jj&1)*2 + 0] = pkbf(p1, p0) + wa[jj];
                Pa[jj>>1][(jj&1)*2 + 1] = pkbf(p3, p2) + wa[jj];
            }

            #pragma unroll
            for (int nfd = 0; nfd < 4; ++nfd) {
                u32 vb[4];
                ldsm4t(vb, voff[nfd] + hofs);
                mmabf(O[nfd], Pa[0], vb[0], vb[1]);
                mmabf(O[nfd], Pa[1], vb[2], vb[3]);
            }
            // weighted row-sum (softmax denominator) on the tensor pipe
            mmabf(Dl, Pa[0], ONESB, ONESB);
            mmabf(Dl, Pa[1], ONESB, ONESB);
        }
    }

    float gam = gamma[0];
    {
        float inv0 = 1.f / Dl[0];
        float inv1 = 1.f / Dl[2];
        int r0 = qbase + g;
        int r1 = r0 + 8;
        #pragma unroll
        for (int nfd = 0; nfd < 4; ++nfd) {
            int col = h*DK + nfd*8 + 2*t4;
            if (r0 < HW) {
                size_t base = ((size_t)(b*HW + r0))*CC + col;
                out[base]     = fmaf(gam, O[nfd][0]*inv0, x[base]);
                out[base + 1] = fmaf(gam, O[nfd][1]*inv0, x[base + 1]);
            }
            if (r1 < HW) {
                size_t base = ((size_t)(b*HW + r1))*CC + col;
                out[base]     = fmaf(gam, O[nfd][2]*inv1, x[base]);
                out[base + 1] = fmaf(gam, O[nfd][3]*inv1, x[base + 1]);
            }
        }
    }
}

extern "C" void kernel_launch(void* const* d_in, const int* in_sizes, int n_in,
                              void* d_out, int out_size) {
    const float* x     = (const float*)d_in[0];
    const float* Wq    = (const float*)d_in[1];
    const float* bq    = (const float*)d_in[2];
    const float* Wk    = (const float*)d_in[3];
    const float* bk    = (const float*)d_in[4];
    const float* Wv    = (const float*)d_in[5];
    const float* bv    = (const float*)d_in[6];
    const float* gamma = (const float*)d_in[7];
    float* out = (float*)d_out;

    prep_x<<<(BB*HW*64 + 255)/256, 256>>>(x);
    prep_w<<<dim3(8, 8, 3), 256>>>(Wq, Wk, Wv);
    proj_mma<<<dim3(BB*HW/32, 3), 256>>>(bq, bk, bv);
    flash_kernel<<<dim3((HW + 127)/128, BB*NH), 256>>>(x, gamma, out);
}

// round 12
// speedup vs baseline: 1.0663x; 1.0380x over previous
#include <cuda_runtime.h>
#include <cuda_bf16.h>

typedef unsigned long long u64;
typedef unsigned int u32;

#define NH    8
#define DK    32
#define HH    56
#define WWID  56
#define HW    3136
#define HW2   1568      // HW/2
#define BB    2
#define CC    256
#define NTILES 49       // 3136 / 64 exactly
#define PADB  80        // smem row stride in BYTES (40 bf16)
#define BUFB  (64*PADB) // one tile buffer bytes
#define LOG2E 1.4426950408889634f
#define ONESB 0x3f803f80u
#define XROWB 544       // proj smem x-row stride in bytes (512 data + 32 pad)

// ---------------- scratch (__device__ globals; no allocs allowed) ----------------
__device__ __align__(16) __nv_bfloat16 g_xh[(size_t)BB*HW*CC];   // permuted frag layout
__device__ __align__(16) __nv_bfloat16 g_Wc[3*CC*512];           // [z][n][kc][t4] -> {h0,h1,l0,l1} u32s
__device__ __align__(16) __nv_bfloat16 g_Qh[(size_t)BB*NH*HW*DK];   // pre-scaled by log2e
__device__ __align__(16) __nv_bfloat16 g_Kb[(size_t)BB*NH*HW*DK];
__device__ __align__(16) __nv_bfloat16 g_Vb[(size_t)BB*NH*HW*DK];
__device__ __align__(16) u32 g_wadd[HW2];   // [tile][half][t4][jj] packed bf16x2 exponent addends

// ---------------- helpers ----------------
__device__ __forceinline__ u32 pkbf(float hi, float lo) {
    u32 r; asm("cvt.rn.bf16x2.f32 %0, %1, %2;" : "=r"(r) : "f"(hi), "f"(lo)); return r;
}
__device__ __forceinline__ float ex2f(float x) {
    float r; asm("ex2.approx.f32 %0, %1;" : "=f"(r) : "f"(x)); return r;
}
__device__ __forceinline__ void ldsm4(u32* r, u32 addr) {
    asm volatile("ldmatrix.sync.aligned.m8n8.x4.shared.b16 {%0,%1,%2,%3}, [%4];"
        : "=r"(r[0]),"=r"(r[1]),"=r"(r[2]),"=r"(r[3]) : "r"(addr));
}
__device__ __forceinline__ void ldsm4t(u32* r, u32 addr) {
    asm volatile("ldmatrix.sync.aligned.m8n8.x4.trans.shared.b16 {%0,%1,%2,%3}, [%4];"
        : "=r"(r[0]),"=r"(r[1]),"=r"(r[2]),"=r"(r[3]) : "r"(addr));
}
__device__ __forceinline__ void mmabf(float* d, const u32* a, u32 b0, u32 b1) {
    asm volatile("mma.sync.aligned.m16n8k16.row.col.f32.bf16.bf16.f32 "
        "{%0,%1,%2,%3}, {%4,%5,%6,%7}, {%8,%9}, {%0,%1,%2,%3};"
        : "+f"(d[0]),"+f"(d[1]),"+f"(d[2]),"+f"(d[3])
        : "r"(a[0]),"r"(a[1]),"r"(a[2]),"r"(a[3]), "r"(b0),"r"(b1));
}
// D = A*B + Z (separate C operand; Z holds a persistent zero quad -> no per-use MOVs)
__device__ __forceinline__ void mmabf_z(float* d, const u32* a, u32 b0, u32 b1, const float* z) {
    asm volatile("mma.sync.aligned.m16n8k16.row.col.f32.bf16.bf16.f32 "
        "{%0,%1,%2,%3}, {%4,%5,%6,%7}, {%8,%9}, {%10,%11,%12,%13};"
        : "=f"(d[0]),"=f"(d[1]),"=f"(d[2]),"=f"(d[3])
        : "r"(a[0]),"r"(a[1]),"r"(a[2]),"r"(a[3]), "r"(b0),"r"(b1),
          "f"(z[0]),"f"(z[1]),"f"(z[2]),"f"(z[3]));
}
__device__ __forceinline__ void cpa16(u32 dst, const void* src) {
    asm volatile("cp.async.cg.shared.global [%0], [%1], 16;" :: "r"(dst), "l"(src));
}
// permuted u32-index within a 128-u32 row: frag order so (t4, t4+4) are adjacent
__device__ __forceinline__ int permj(int j) {
    int t = j & 7, kc = j >> 3;
    return kc*8 + ((t < 4) ? 2*t : 2*(t-4) + 1);
}
__device__ __forceinline__ int lww(int v) {
    return ((v >= 1 && v <= 3) || (v >= 52 && v <= 54)) ? 1 : 0;
}

// ---------------- prep: x -> bf16 hi (permuted) + multiplicity table (fused) ----------------
__global__ __launch_bounds__(256) void prep_x(const float* __restrict__ x) {
    int idx = blockIdx.x*256 + threadIdx.x;       // over BB*HW*64 float4s
    if (idx < HW2) {
        // element e=idx of [tile][half][t4][jj] layout holds pair p = tile*32+half*16+jj*4+t4
        int jj = idx & 3, t4i = (idx >> 2) & 3, half = (idx >> 4) & 1, tile = idx >> 5;
        int p = tile*32 + half*16 + jj*4 + t4i;
        int k0 = 2*p, k1 = k0 + 1;
        int y0 = k0 / WWID, x0 = k0 - y0*WWID;
        int y1 = k1 / WWID, x1 = k1 - y1*WWID;
        u32 w0 = (u32)(lww(y0) + lww(x0));
        u32 w1 = (u32)(lww(y1) + lww(x1));
        g_wadd[idx] = (w0 << 7) | (w1 << 23);
    }
    if (idx >= BB*HW*64) return;
    int row = idx >> 6, i = idx & 63;
    float4 v = reinterpret_cast<const float4*>(x)[idx];
    u32 H0 = pkbf(v.y, v.x);
    u32 H1 = pkbf(v.w, v.z);
    u32* xh = reinterpret_cast<u32*>(g_xh) + (size_t)row*128;
    xh[permj(2*i)]     = H0;
    xh[permj(2*i + 1)] = H1;
}

// ---------------- prep: W -> transposed/permuted, interleaved hi|lo u128 entries ----------------
__global__ __launch_bounds__(256) void prep_w(const float* __restrict__ Wq,
                                              const float* __restrict__ Wk,
                                              const float* __restrict__ Wv) {
    __shared__ float T[32][33];
    int z = blockIdx.z;
    const float* W = (z == 0) ? Wq : (z == 1) ? Wk : Wv;
    float sc = (z == 0) ? LOG2E : 1.0f;
    int k0 = blockIdx.y*32, n0 = blockIdx.x*32;
    int tx = threadIdx.x & 31, ty = threadIdx.x >> 5;   // 32x8
    #pragma unroll
    for (int i = 0; i < 4; ++i)
        T[ty + 8*i][tx] = W[(size_t)(k0 + ty + 8*i)*CC + n0 + tx];
    __syncthreads();
    #pragma unroll
    for (int i = 0; i < 4; ++i) {
        int n = n0 + ty + 8*i, k = k0 + tx;
        float v = T[tx][ty + 8*i] * sc;
        __nv_bfloat16 h = __float2bfloat16(v);
        __nv_bfloat16 l = __float2bfloat16(v - __bfloat162float(h));
        int j = k >> 1;
        int kc = j >> 3, t = j & 7;
        int pj = (t < 4) ? 2*t : 2*(t - 4) + 1;
        int t4 = pj >> 1, sub = pj & 1;
        size_t e = (((size_t)z*CC + n)*16 + kc)*4 + t4;   // u128 entry
        size_t slot = e*8 + sub*2 + (k & 1);              // h at bytes 0-7
        g_Wc[slot]     = h;
        g_Wc[slot + 4] = l;                                // l at bytes 8-15
    }
}

// ---------------- tensor-core projections: smem-staged x, u128 W loads (round-9 proven) ----------------
// z=0: Q -> g_Qh (log2e-scaled) ; z=1: K -> g_Kb ; z=2: V -> g_Vb
__global__ __launch_bounds__(256) void proj_mma(const float* __restrict__ bq,
                                                const float* __restrict__ bk,
                                                const float* __restrict__ bv) {
    __shared__ __align__(16) char sX[32*XROWB];           // 17.4 KB x tile
    int z = blockIdx.y;
    int m0 = blockIdx.x * 32;
    int tid = threadIdx.x, wid = tid >> 5, lane = tid & 31;
    int g = lane >> 2, t4 = lane & 3;
    int n0 = wid * 32;
    const float* bias = (z == 0) ? bq : (z == 1) ? bk : bv;
    float bscale = (z == 0) ? LOG2E : 1.0f;
    __nv_bfloat16* dst = (z == 0) ? g_Qh : (z == 1) ? g_Kb : g_Vb;

    // stage x tile: 32 rows x 512B, 16B chunks
    u32 sxb = (u32)__cvta_generic_to_shared(sX);
    const char* xsrc = (const char*)g_xh + (size_t)m0*512;
    #pragma unroll
    for (int rep = 0; rep < 4; ++rep) {
        int i = tid + rep*256;                  // 0..1023
        int row = i >> 5, c = i & 31;
        cpa16(sxb + row*XROWB + c*16, xsrc + (size_t)row*512 + c*16);
    }
    asm volatile("cp.async.commit_group;");

    int rl[4];
    #pragma unroll
    for (int t = 0; t < 4; ++t)
        rl[t] = (t >> 1)*16 + (t & 1)*8 + g;    // local rows

    const uint4* wc = reinterpret_cast<const uint4*>(g_Wc) + (size_t)z*CC*64;

    float acc[2][4][4];
    #pragma unroll
    for (int mf = 0; mf < 2; ++mf)
        #pragma unroll
        for (int nf = 0; nf < 4; ++nf)
            #pragma unroll
            for (int c = 0; c < 4; ++c) acc[mf][nf][c] = 0.f;

    asm volatile("cp.async.wait_group 0;");
    __syncthreads();

    const char* sxp = sX;
    #pragma unroll 4
    for (int kc = 0; kc < 16; ++kc) {
        u32 ah[2][4];
        #pragma unroll
        for (int mf = 0; mf < 2; ++mf) {
            u64 va0 = *(const u64*)(sxp + rl[mf*2]    *XROWB + kc*32 + t4*8);
            u64 va1 = *(const u64*)(sxp + rl[mf*2 + 1]*XROWB + kc*32 + t4*8);
            ah[mf][0] = (u32)va0; ah[mf][2] = (u32)(va0 >> 32);
            ah[mf][1] = (u32)va1; ah[mf][3] = (u32)(va1 >> 32);
        }
        #pragma unroll
        for (int nf = 0; nf < 4; ++nf) {
            int nrow = n0 + nf*8 + g;
            uint4 w = wc[(size_t)nrow*64 + kc*4 + t4];
            #pragma unroll
            for (int mf = 0; mf < 2; ++mf) {
                mmabf(acc[mf][nf], ah[mf], w.x, w.y);
                mmabf(acc[mf][nf], ah[mf], w.z, w.w);
            }
        }
    }

    #pragma unroll
    for (int nf = 0; nf < 4; ++nf) {
        int n = n0 + nf*8 + 2*t4;
        float bi0 = bias[n]*bscale, bi1 = bias[n + 1]*bscale;
        int hh = n >> 5, dd = n & 31;
        #pragma unroll
        for (int mf = 0; mf < 2; ++mf) {
            #pragma unroll
            for (int half = 0; half < 2; ++half) {
                int t = mf*2 + half;
                int r = m0 + rl[t];
                int b = r / HW, q = r - b*HW;
                float v0 = acc[mf][nf][half*2]     + bi0;
                float v1 = acc[mf][nf][half*2 + 1] + bi1;
                u32 Hp = pkbf(v1, v0);
                size_t o = ((size_t)(b*NH + hh)*HW + q)*16 + (dd >> 1);
                reinterpret_cast<u32*>(dst)[o] = Hp;
            }
        }
    }
}

// ---------------- tensor-core flash attention: 4 warps, 32 q/warp, unique keys ----------------
__global__ __launch_bounds__(128, 4) void flash_kernel(const float* __restrict__ x,
                                                       const float* __restrict__ gamma,
                                                       float* __restrict__ out) {
    __shared__ __align__(16) __nv_bfloat16 sK[2*BUFB/2];
    __shared__ __align__(16) __nv_bfloat16 sV[2*BUFB/2];
    __shared__ __align__(16) u32 sWadd[HW2];
    int bh = blockIdx.y;
    int b = bh >> 3, h = bh & 7;
    int tid = threadIdx.x, wid = tid >> 5, lane = tid & 31;
    int g = lane >> 2, t4 = lane & 3;
    int qbase = blockIdx.x*128 + wid*32;

    for (int i = tid; i < HW2; i += 128) sWadd[i] = g_wadd[i];

    u32 qh[2][2][4];
    #pragma unroll
    for (int mf = 0; mf < 2; ++mf) {
        int r0 = qbase + mf*16 + g;     if (r0 >= HW) r0 = 0;
        int r1 = qbase + mf*16 + g + 8; if (r1 >= HW) r1 = 0;
        const u32* h0 = (const u32*)(g_Qh + (((size_t)bh)*HW + r0)*DK);
        const u32* h1 = (const u32*)(g_Qh + (((size_t)bh)*HW + r1)*DK);
        #pragma unroll
        for (int kf = 0; kf < 2; ++kf) {
            qh[mf][kf][0] = h0[kf*8 + t4];
            qh[mf][kf][1] = h1[kf*8 + t4];
            qh[mf][kf][2] = h0[kf*8 + 4 + t4];
            qh[mf][kf][3] = h1[kf*8 + 4 + t4];
        }
    }

    float O[2][4][4];
    float Dl[2][4];
    float zq[4] = {0.f, 0.f, 0.f, 0.f};   // persistent zero quad for mmabf_z
    #pragma unroll
    for (int mf = 0; mf < 2; ++mf) {
        #pragma unroll
        for (int c = 0; c < 4; ++c) Dl[mf][c] = 0.f;
        #pragma unroll
        for (int nf = 0; nf < 4; ++nf)
            #pragma unroll
            for (int c = 0; c < 4; ++c) O[mf][nf][c] = 0.f;
    }

    const float4* Kg = (const float4*)(g_Kb + ((size_t)bh)*HW*DK);
    const float4* Vg = (const float4*)(g_Vb + ((size_t)bh)*HW*DK);
    u32 skb = (u32)__cvta_generic_to_shared(sK);
    u32 svb = (u32)__cvta_generic_to_shared(sV);
    const uint4* sW4 = reinterpret_cast<const uint4*>(sWadd);

    u32 koff[4], voff[4];
    #pragma unroll
    for (int nf = 0; nf < 4; ++nf) {
        koff[nf] = skb + (nf*8 + (lane & 7))*PADB + (lane >> 3)*16;
        voff[nf] = svb + lane*PADB + nf*16;
    }
    u32 wk = skb + (tid >> 2)*PADB + (tid & 3)*16;
    u32 wv = svb + (tid >> 2)*PADB + (tid & 3)*16;

    // prologue: tile 0 -> buf 0 (128 threads cover 256 float4s in 2 steps)
    cpa16(wk,            Kg + tid);
    cpa16(wk + 32*PADB,  Kg + tid + 128);
    cpa16(wv,            Vg + tid);
    cpa16(wv + 32*PADB,  Vg + tid + 128);
    asm volatile("cp.async.commit_group;");

    for (int tile = 0; tile < NTILES; ++tile) {
        u32 bofs = (tile & 1)*BUFB;
        asm volatile("cp.async.wait_group 0;");
        __syncthreads();
        if (tile + 1 < NTILES) {
            u32 nofs = ((tile + 1) & 1)*BUFB;
            const float4* Kn = Kg + (size_t)(tile + 1)*256;
            const float4* Vn = Vg + (size_t)(tile + 1)*256;
            cpa16(wk + nofs,           Kn + tid);
            cpa16(wk + nofs + 32*PADB, Kn + tid + 128);
            cpa16(wv + nofs,           Vn + tid);
            cpa16(wv + nofs + 32*PADB, Vn + tid + 128);
            asm volatile("cp.async.commit_group;");
        }

        #pragma unroll
        for (int half = 0; half < 2; ++half) {
            u32 hofs = bofs + half*(32*PADB);
            float S[2][4][4];

            #pragma unroll
            for (int nf = 0; nf < 4; ++nf) {
                u32 bhr[4];
                ldsm4(bhr, koff[nf] + hofs);
                #pragma unroll
                for (int mf = 0; mf < 2; ++mf) {
                    mmabf_z(S[mf][nf], qh[mf][0], bhr[0], bhr[1], zq);
                    mmabf(S[mf][nf], qh[mf][1], bhr[2], bhr[3]);
                }
            }

            uint4 wv4 = sW4[(tile*2 + half)*4 + t4];
            u32 wa[4] = {wv4.x, wv4.y, wv4.z, wv4.w};

            u32 Pa[2][2][4];
            #pragma unroll
            for (int mf = 0; mf < 2; ++mf)
                #pragma unroll
                for (int jj = 0; jj < 4; ++jj) {
                    float p0 = ex2f(S[mf][jj][0]);
                    float p1 = ex2f(S[mf][jj][1]);
                    float p2 = ex2f(S[mf][jj][2]);
                    float p3 = ex2f(S[mf][jj][3]);
                    // exact multiplicity weighting: +w in the bf16 exponent field
                    Pa[mf][jj>>1][(jj&1)*2 + 0] = pkbf(p1, p0) + wa[jj];
                    Pa[mf][jj>>1][(jj&1)*2 + 1] = pkbf(p3, p2) + wa[jj];
                }

            #pragma unroll
            for (int nfd = 0; nfd < 4; ++nfd) {
                u32 vb[4];
                ldsm4t(vb, voff[nfd] + hofs);
                #pragma unroll
                for (int mf = 0; mf < 2; ++mf) {
                    mmabf(O[mf][nfd], Pa[mf][0], vb[0], vb[1]);
                    mmabf(O[mf][nfd], Pa[mf][1], vb[2], vb[3]);
                }
            }
            // weighted row-sum (softmax denominator) on the tensor pipe
            #pragma unroll
            for (int mf = 0; mf < 2; ++mf) {
                mmabf(Dl[mf], Pa[mf][0], ONESB, ONESB);
                mmabf(Dl[mf], Pa[mf][1], ONESB, ONESB);
            }
        }
    }

    float gam = gamma[0];
    #pragma unroll
    for (int mf = 0; mf < 2; ++mf) {
        float inv0 = 1.f / Dl[mf][0];
        float inv1 = 1.f / Dl[mf][2];
        int r0 = qbase + mf*16 + g;
        int r1 = r0 + 8;
        #pragma unroll
        for (int nfd = 0; nfd < 4; ++nfd) {
            int col = h*DK + nfd*8 + 2*t4;
            if (r0 < HW) {
                size_t base = ((size_t)(b*HW + r0))*CC + col;
                out[base]     = fmaf(gam, O[mf][nfd][0]*inv0, x[base]);
                out[base + 1] = fmaf(gam, O[mf][nfd][1]*inv0, x[base + 1]);
            }
            if (r1 < HW) {
                size_t base = ((size_t)(b*HW + r1))*CC + col;
                out[base]     = fmaf(gam, O[mf][nfd][2]*inv1, x[base]);
                out[base + 1] = fmaf(gam, O[mf][nfd][3]*inv1, x[base + 1]);
            }
        }
    }
}

extern "C" void kernel_launch(void* const* d_in, const int* in_sizes, int n_in,
                              void* d_out, int out_size) {
    const float* x     = (const float*)d_in[0];
    const float* Wq    = (const float*)d_in[1];
    const float* bq    = (const float*)d_in[2];
    const float* Wk    = (const float*)d_in[3];
    const float* bk    = (const float*)d_in[4];
    const float* Wv    = (const float*)d_in[5];
    const float* bv    = (const float*)d_in[6];
    const float* gamma = (const float*)d_in[7];
    float* out = (float*)d_out;

    prep_x<<<(BB*HW*64 + 255)/256, 256>>>(x);
    prep_w<<<dim3(8, 8, 3), 256>>>(Wq, Wk, Wv);
    proj_mma<<<dim3(BB*HW/32, 3), 256>>>(bq, bk, bv);
    flash_kernel<<<dim3((HW + 127)/128, BB*NH), 128>>>(x, gamma, out);
}

// round 17
// speedup vs baseline: 1.1036x; 1.0350x over previous
#include <cuda_runtime.h>
#include <cuda_bf16.h>

typedef unsigned long long u64;
typedef unsigned int u32;

#define NH    8
#define DK    32
#define HH    56
#define WWID  56
#define HW    3136
#define HW2   1568      // HW/2
#define BB    2
#define CC    256
#define NTILES 49       // 3136 / 64 exactly
#define PADB  80        // smem row stride in BYTES (40 bf16)
#define BUFB  (64*PADB) // one tile buffer bytes
#define LOG2E 1.4426950408889634f
#define ONESB 0x3f803f80u
#define XROWB 544       // proj smem x-row stride in bytes (512 data + 32 pad)
#define NXBLK 1568      // prep blocks doing x-conversion

// ---------------- scratch (__device__ globals; no allocs allowed) ----------------
__device__ __align__(16) __nv_bfloat16 g_xh[(size_t)BB*HW*CC];   // permuted frag layout
__device__ __align__(16) __nv_bfloat16 g_Wc[3*CC*512];           // [z][n][kc][t4] -> {h0,h1,l0,l1} u32s
__device__ __align__(16) __nv_bfloat16 g_Qh[(size_t)BB*NH*HW*DK];   // pre-scaled by log2e
__device__ __align__(16) __nv_bfloat16 g_Kb[(size_t)BB*NH*HW*DK];
__device__ __align__(16) __nv_bfloat16 g_Vb[(size_t)BB*NH*HW*DK];
__device__ __align__(16) u32 g_wadd[HW2];   // [tile][half][t4][jj] packed bf16x2 exponent addends

// ---------------- helpers ----------------
__device__ __forceinline__ u32 pkbf(float hi, float lo) {
    u32 r; asm("cvt.rn.bf16x2.f32 %0, %1, %2;" : "=r"(r) : "f"(hi), "f"(lo)); return r;
}
__device__ __forceinline__ float ex2f(float x) {
    float r; asm("ex2.approx.f32 %0, %1;" : "=f"(r) : "f"(x)); return r;
}
__device__ __forceinline__ void ldsm4(u32* r, u32 addr) {
    asm volatile("ldmatrix.sync.aligned.m8n8.x4.shared.b16 {%0,%1,%2,%3}, [%4];"
        : "=r"(r[0]),"=r"(r[1]),"=r"(r[2]),"=r"(r[3]) : "r"(addr));
}
__device__ __forceinline__ void ldsm4t(u32* r, u32 addr) {
    asm volatile("ldmatrix.sync.aligned.m8n8.x4.trans.shared.b16 {%0,%1,%2,%3}, [%4];"
        : "=r"(r[0]),"=r"(r[1]),"=r"(r[2]),"=r"(r[3]) : "r"(addr));
}
__device__ __forceinline__ void mmabf(float* d, const u32* a, u32 b0, u32 b1) {
    asm volatile("mma.sync.aligned.m16n8k16.row.col.f32.bf16.bf16.f32 "
        "{%0,%1,%2,%3}, {%4,%5,%6,%7}, {%8,%9}, {%0,%1,%2,%3};"
        : "+f"(d[0]),"+f"(d[1]),"+f"(d[2]),"+f"(d[3])
        : "r"(a[0]),"r"(a[1]),"r"(a[2]),"r"(a[3]), "r"(b0),"r"(b1));
}
// D = A*B + Z (separate C operand; Z holds a persistent zero quad -> no per-use MOVs)
__device__ __forceinline__ void mmabf_z(float* d, const u32* a, u32 b0, u32 b1, const float* z) {
    asm volatile("mma.sync.aligned.m16n8k16.row.col.f32.bf16.bf16.f32 "
        "{%0,%1,%2,%3}, {%4,%5,%6,%7}, {%8,%9}, {%10,%11,%12,%13};"
        : "=f"(d[0]),"=f"(d[1]),"=f"(d[2]),"=f"(d[3])
        : "r"(a[0]),"r"(a[1]),"r"(a[2]),"r"(a[3]), "r"(b0),"r"(b1),
          "f"(z[0]),"f"(z[1]),"f"(z[2]),"f"(z[3]));
}
__device__ __forceinline__ void cpa16(u32 dst, const void* src) {
    asm volatile("cp.async.cg.shared.global [%0], [%1], 16;" :: "r"(dst), "l"(src));
}
// permuted u32-index within a 128-u32 row: frag order so (t4, t4+4) are adjacent
__device__ __forceinline__ int permj(int j) {
    int t = j & 7, kc = j >> 3;
    return kc*8 + ((t < 4) ? 2*t : 2*(t-4) + 1);
}
__device__ __forceinline__ int lww(int v) {
    return ((v >= 1 && v <= 3) || (v >= 52 && v <= 54)) ? 1 : 0;
}

// ---------------- fused prep: blocks [0,NXBLK): x->bf16 + wadd ; [NXBLK,+192): W transform ----------------
__global__ __launch_bounds__(256) void prep_all(const float* __restrict__ x,
                                                const float* __restrict__ Wq,
                                                const float* __restrict__ Wk,
                                                const float* __restrict__ Wv) {
    if (blockIdx.x < NXBLK) {
        int idx = blockIdx.x*256 + threadIdx.x;       // over BB*HW*64 float4s
        if (idx < HW2) {
            // element e=idx of [tile][half][t4][jj] layout holds pair p = tile*32+half*16+jj*4+t4
            int jj = idx & 3, t4i = (idx >> 2) & 3, half = (idx >> 4) & 1, tile = idx >> 5;
            int p = tile*32 + half*16 + jj*4 + t4i;
            int k0 = 2*p, k1 = k0 + 1;
            int y0 = k0 / WWID, x0 = k0 - y0*WWID;
            int y1 = k1 / WWID, x1 = k1 - y1*WWID;
            u32 w0 = (u32)(lww(y0) + lww(x0));
            u32 w1 = (u32)(lww(y1) + lww(x1));
            g_wadd[idx] = (w0 << 7) | (w1 << 23);
        }
        if (idx >= BB*HW*64) return;
        int row = idx >> 6, i = idx & 63;
        float4 v = reinterpret_cast<const float4*>(x)[idx];
        u32 H0 = pkbf(v.y, v.x);
        u32 H1 = pkbf(v.w, v.z);
        u32* xh = reinterpret_cast<u32*>(g_xh) + (size_t)row*128;
        xh[permj(2*i)]     = H0;
        xh[permj(2*i + 1)] = H1;
    } else {
        __shared__ float T[32][33];
        int wb = blockIdx.x - NXBLK;                  // 0..191
        int z = wb >> 6;
        int rem = wb & 63;
        int n0 = (rem & 7)*32, k0 = (rem >> 3)*32;
        const float* W = (z == 0) ? Wq : (z == 1) ? Wk : Wv;
        float sc = (z == 0) ? LOG2E : 1.0f;
        int tx = threadIdx.x & 31, ty = threadIdx.x >> 5;   // 32x8
        #pragma unroll
        for (int i = 0; i < 4; ++i)
            T[ty + 8*i][tx] = W[(size_t)(k0 + ty + 8*i)*CC + n0 + tx];
        __syncthreads();
        #pragma unroll
        for (int i = 0; i < 4; ++i) {
            int n = n0 + ty + 8*i, k = k0 + tx;
            float v = T[tx][ty + 8*i] * sc;
            __nv_bfloat16 h = __float2bfloat16(v);
            __nv_bfloat16 l = __float2bfloat16(v - __bfloat162float(h));
            int j = k >> 1;
            int kc = j >> 3, t = j & 7;
            int pj = (t < 4) ? 2*t : 2*(t - 4) + 1;
            int t4 = pj >> 1, sub = pj & 1;
            size_t e = (((size_t)z*CC + n)*16 + kc)*4 + t4;   // u128 entry
            size_t slot = e*8 + sub*2 + (k & 1);              // h at bytes 0-7
            g_Wc[slot]     = h;
            g_Wc[slot + 4] = l;                                // l at bytes 8-15
        }
    }
}

// ---------------- tensor-core projections: smem-staged x, u128 W loads, 4 CTAs/SM ----------------
// z=0: Q -> g_Qh (log2e-scaled) ; z=1: K -> g_Kb ; z=2: V -> g_Vb
__global__ __launch_bounds__(256, 4) void proj_mma(const float* __restrict__ bq,
                                                   const float* __restrict__ bk,
                                                   const float* __restrict__ bv) {
    __shared__ __align__(16) char sX[32*XROWB];           // 17.4 KB x tile
    int z = blockIdx.y;
    int m0 = blockIdx.x * 32;
    int tid = threadIdx.x, wid = tid >> 5, lane = tid & 31;
    int g = lane >> 2, t4 = lane & 3;
    int n0 = wid * 32;
    const float* bias = (z == 0) ? bq : (z == 1) ? bk : bv;
    float bscale = (z == 0) ? LOG2E : 1.0f;
    __nv_bfloat16* dst = (z == 0) ? g_Qh : (z == 1) ? g_Kb : g_Vb;

    // stage x tile: 32 rows x 512B, 16B chunks
    u32 sxb = (u32)__cvta_generic_to_shared(sX);
    const char* xsrc = (const char*)g_xh + (size_t)m0*512;
    #pragma unroll
    for (int rep = 0; rep < 4; ++rep) {
        int i = tid + rep*256;                  // 0..1023
        int row = i >> 5, c = i & 31;
        cpa16(sxb + row*XROWB + c*16, xsrc + (size_t)row*512 + c*16);
    }
    asm volatile("cp.async.commit_group;");

    int rl[4];
    #pragma unroll
    for (int t = 0; t < 4; ++t)
        rl[t] = (t >> 1)*16 + (t & 1)*8 + g;    // local rows

    const uint4* wc = reinterpret_cast<const uint4*>(g_Wc) + (size_t)z*CC*64;

    float acc[2][4][4];
    #pragma unroll
    for (int mf = 0; mf < 2; ++mf)
        #pragma unroll
        for (int nf = 0; nf < 4; ++nf)
            #pragma unroll
            for (int c = 0; c < 4; ++c) acc[mf][nf][c] = 0.f;

    asm volatile("cp.async.wait_group 0;");
    __syncthreads();

    const char* sxp = sX;
    #pragma unroll 4
    for (int kc = 0; kc < 16; ++kc) {
        u32 ah[2][4];
        #pragma unroll
        for (int mf = 0; mf < 2; ++mf) {
            u64 va0 = *(const u64*)(sxp + rl[mf*2]    *XROWB + kc*32 + t4*8);
            u64 va1 = *(const u64*)(sxp + rl[mf*2 + 1]*XROWB + kc*32 + t4*8);
            ah[mf][0] = (u32)va0; ah[mf][2] = (u32)(va0 >> 32);
            ah[mf][1] = (u32)va1; ah[mf][3] = (u32)(va1 >> 32);
        }
        #pragma unroll
        for (int nf = 0; nf < 4; ++nf) {
            int nrow = n0 + nf*8 + g;
            uint4 w = wc[(size_t)nrow*64 + kc*4 + t4];
            #pragma unroll
            for (int mf = 0; mf < 2; ++mf) {
                mmabf(acc[mf][nf], ah[mf], w.x, w.y);
                mmabf(acc[mf][nf], ah[mf], w.z, w.w);
            }
        }
    }

    #pragma unroll
    for (int nf = 0; nf < 4; ++nf) {
        int n = n0 + nf*8 + 2*t4;
        float bi0 = bias[n]*bscale, bi1 = bias[n + 1]*bscale;
        int hh = n >> 5, dd = n & 31;
        #pragma unroll
        for (int mf = 0; mf < 2; ++mf) {
            #pragma unroll
            for (int half = 0; half < 2; ++half) {
                int t = mf*2 + half;
                int r = m0 + rl[t];
                int b = r / HW, q = r - b*HW;
                float v0 = acc[mf][nf][half*2]     + bi0;
                float v1 = acc[mf][nf][half*2 + 1] + bi1;
                u32 Hp = pkbf(v1, v0);
                size_t o = ((size_t)(b*NH + hh)*HW + q)*16 + (dd >> 1);
                reinterpret_cast<u32*>(dst)[o] = Hp;
            }
        }
    }
}

// ---------------- tensor-core flash attention: 4 warps, 32 q/warp, unique keys ----------------
__global__ __launch_bounds__(128, 4) void flash_kernel(const float* __restrict__ x,
                                                       const float* __restrict__ gamma,
                                                       float* __restrict__ out) {
    __shared__ __align__(16) __nv_bfloat16 sK[2*BUFB/2];
    __shared__ __align__(16) __nv_bfloat16 sV[2*BUFB/2];
    __shared__ __align__(16) u32 sWadd[HW2];
    int bh = blockIdx.y;
    int b = bh >> 3, h = bh & 7;
    int tid = threadIdx.x, wid = tid >> 5, lane = tid & 31;
    int g = lane >> 2, t4 = lane & 3;
    int qbase = blockIdx.x*128 + wid*32;

    for (int i = tid; i < HW2; i += 128) sWadd[i] = g_wadd[i];

    u32 qh[2][2][4];
    #pragma unroll
    for (int mf = 0; mf < 2; ++mf) {
        int r0 = qbase + mf*16 + g;     if (r0 >= HW) r0 = 0;
        int r1 = qbase + mf*16 + g + 8; if (r1 >= HW) r1 = 0;
        const u32* h0 = (const u32*)(g_Qh + (((size_t)bh)*HW + r0)*DK);
        const u32* h1 = (const u32*)(g_Qh + (((size_t)bh)*HW + r1)*DK);
        #pragma unroll
        for (int kf = 0; kf < 2; ++kf) {
            qh[mf][kf][0] = h0[kf*8 + t4];
            qh[mf][kf][1] = h1[kf*8 + t4];
            qh[mf][kf][2] = h0[kf*8 + 4 + t4];
            qh[mf][kf][3] = h1[kf*8 + 4 + t4];
        }
    }

    float O[2][4][4];
    float Dl[2][4];
    float zq[4] = {0.f, 0.f, 0.f, 0.f};   // persistent zero quad for mmabf_z
    #pragma unroll
    for (int mf = 0; mf < 2; ++mf) {
        #pragma unroll
        for (int c = 0; c < 4; ++c) Dl[mf][c] = 0.f;
        #pragma unroll
        for (int nf = 0; nf < 4; ++nf)
            #pragma unroll
            for (int c = 0; c < 4; ++c) O[mf][nf][c] = 0.f;
    }

    const float4* Kg = (const float4*)(g_Kb + ((size_t)bh)*HW*DK);
    const float4* Vg = (const float4*)(g_Vb + ((size_t)bh)*HW*DK);
    u32 skb = (u32)__cvta_generic_to_shared(sK);
    u32 svb = (u32)__cvta_generic_to_shared(sV);
    const uint4* sW4 = reinterpret_cast<const uint4*>(sWadd);

    u32 koff[4], voff[4];
    #pragma unroll
    for (int nf = 0; nf < 4; ++nf) {
        koff[nf] = skb + (nf*8 + (lane & 7))*PADB + (lane >> 3)*16;
        voff[nf] = svb + lane*PADB + nf*16;
    }
    u32 wk = skb + (tid >> 2)*PADB + (tid & 3)*16;
    u32 wv = svb + (tid >> 2)*PADB + (tid & 3)*16;

    // prologue: tile 0 -> buf 0 (128 threads cover 256 float4s in 2 steps)
    cpa16(wk,            Kg + tid);
    cpa16(wk + 32*PADB,  Kg + tid + 128);
    cpa16(wv,            Vg + tid);
    cpa16(wv + 32*PADB,  Vg + tid + 128);
    asm volatile("cp.async.commit_group;");

    for (int tile = 0; tile < NTILES; ++tile) {
        u32 bofs = (tile & 1)*BUFB;
        asm volatile("cp.async.wait_group 0;");
        __syncthreads();
        if (tile + 1 < NTILES) {
            u32 nofs = ((tile + 1) & 1)*BUFB;
            const float4* Kn = Kg + (size_t)(tile + 1)*256;
            const float4* Vn = Vg + (size_t)(tile + 1)*256;
            cpa16(wk + nofs,           Kn + tid);
            cpa16(wk + nofs + 32*PADB, Kn + tid + 128);
            cpa16(wv + nofs,           Vn + tid);
            cpa16(wv + nofs + 32*PADB, Vn + tid + 128);
            asm volatile("cp.async.commit_group;");
        }

        #pragma unroll
        for (int half = 0; half < 2; ++half) {
            u32 hofs = bofs + half*(32*PADB);
            float S[2][4][4];

            #pragma unroll
            for (int nf = 0; nf < 4; ++nf) {
                u32 bhr[4];
                ldsm4(bhr, koff[nf] + hofs);
                #pragma unroll
                for (int mf = 0; mf < 2; ++mf) {
                    mmabf_z(S[mf][nf], qh[mf][0], bhr[0], bhr[1], zq);
                    mmabf(S[mf][nf], qh[mf][1], bhr[2], bhr[3]);
                }
            }

            uint4 wv4 = sW4[(tile*2 + half)*4 + t4];
            u32 wa[4] = {wv4.x, wv4.y, wv4.z, wv4.w};

            u32 Pa[2][2][4];
            #pragma unroll
            for (int mf = 0; mf < 2; ++mf)
                #pragma unroll
                for (int jj = 0; jj < 4; ++jj) {
                    float p0 = ex2f(S[mf][jj][0]);
                    float p1 = ex2f(S[mf][jj][1]);
                    float p2 = ex2f(S[mf][jj][2]);
                    float p3 = ex2f(S[mf][jj][3]);
                    // exact multiplicity weighting: +w in the bf16 exponent field
                    Pa[mf][jj>>1][(jj&1)*2 + 0] = pkbf(p1, p0) + wa[jj];
                    Pa[mf][jj>>1][(jj&1)*2 + 1] = pkbf(p3, p2) + wa[jj];
                }

            #pragma unroll
            for (int nfd = 0; nfd < 4; ++nfd) {
                u32 vb[4];
                ldsm4t(vb, voff[nfd] + hofs);
                #pragma unroll
                for (int mf = 0; mf < 2; ++mf) {
                    mmabf(O[mf][nfd], Pa[mf][0], vb[0], vb[1]);
                    mmabf(O[mf][nfd], Pa[mf][1], vb[2], vb[3]);
                }
            }
            // weighted row-sum (softmax denominator) on the tensor pipe
            #pragma unroll
            for (int mf = 0; mf < 2; ++mf) {
                mmabf(Dl[mf], Pa[mf][0], ONESB, ONESB);
                mmabf(Dl[mf], Pa[mf][1], ONESB, ONESB);
            }
        }
    }

    float gam = gamma[0];
    #pragma unroll
    for (int mf = 0; mf < 2; ++mf) {
        float inv0 = 1.f / Dl[mf][0];
        float inv1 = 1.f / Dl[mf][2];
        int r0 = qbase + mf*16 + g;
        int r1 = r0 + 8;
        #pragma unroll
        for (int nfd = 0; nfd < 4; ++nfd) {
            int col = h*DK + nfd*8 + 2*t4;
            if (r0 < HW) {
                size_t base = ((size_t)(b*HW + r0))*CC + col;
                out[base]     = fmaf(gam, O[mf][nfd][0]*inv0, x[base]);
                out[base + 1] = fmaf(gam, O[mf][nfd][1]*inv0, x[base + 1]);
            }
            if (r1 < HW) {
                size_t base = ((size_t)(b*HW + r1))*CC + col;
                out[base]     = fmaf(gam, O[mf][nfd][2]*inv1, x[base]);
                out[base + 1] = fmaf(gam, O[mf][nfd][3]*inv1, x[base + 1]);
            }
        }
    }
}

extern "C" void kernel_launch(void* const* d_in, const int* in_sizes, int n_in,
                              void* d_out, int out_size) {
    const float* x     = (const float*)d_in[0];
    const float* Wq    = (const float*)d_in[1];
    const float* bq    = (const float*)d_in[2];
    const float* Wk    = (const float*)d_in[3];
    const float* bk    = (const float*)d_in[4];
    const float* Wv    = (const float*)d_in[5];
    const float* bv    = (const float*)d_in[6];
    const float* gamma = (const float*)d_in[7];
    float* out = (float*)d_out;

    prep_all<<<NXBLK + 192, 256>>>(x, Wq, Wk, Wv);
    proj_mma<<<dim3(BB*HW/32, 3), 256>>>(bq, bk, bv);
    flash_kernel<<<dim3((HW + 127)/128, BB*NH), 128>>>(x, gamma, out);
}